// round 6
// baseline (speedup 1.0000x reference)
#include <cuda_runtime.h>
#include <cuda_bf16.h>
#include <math_constants.h>
#include <cstddef>
#include <cstdint>

// Problem constants
#define BB 4
#define TT 2048
#define DD 1024
#define HH 16
#define HD 64

#define KSCALE (0.125f * 1.4426950408889634f)   // 1/sqrt(64) * log2(e)

// ---------------------------------------------------------------------------
// Scratch (device globals: allocation-guard-safe)
// ---------------------------------------------------------------------------
__device__ __nv_bfloat16 g_qhi[(size_t)BB * HH * TT * HD];  // [B,H,T,HD], pre-scaled
__device__ __nv_bfloat16 g_qlo[(size_t)BB * HH * TT * HD];
__device__ __nv_bfloat16 g_khi[(size_t)BB * HH * TT * HD];
__device__ __nv_bfloat16 g_klo[(size_t)BB * HH * TT * HD];
__device__ __nv_bfloat16 g_vhi[(size_t)BB * HH * TT * HD];
__device__ __nv_bfloat16 g_vlo[(size_t)BB * HH * TT * HD];

__device__ __nv_bfloat16 g_xhi[(size_t)BB * TT * DD];
__device__ __nv_bfloat16 g_xlo[(size_t)BB * TT * DD];
__device__ __nv_bfloat16 g_wqhi[(size_t)3 * DD * DD];   // w_qkv^T [3072,1024]
__device__ __nv_bfloat16 g_wqlo[(size_t)3 * DD * DD];
__device__ __nv_bfloat16 g_wohi[(size_t)DD * DD];        // w_out^T [1024,1024]
__device__ __nv_bfloat16 g_wolo[(size_t)DD * DD];
__device__ __nv_bfloat16 g_yhi[(size_t)BB * TT * DD];    // attention out, split
__device__ __nv_bfloat16 g_ylo[(size_t)BB * TT * DD];

#define SWZ128(o) ((o) ^ (((o) >> 3) & 0x70))
#define SWZ64(o)  ((o) ^ (((o) >> 3) & 0x30))

// ---------------------------------------------------------------------------
// mma.sync / cp.async helpers (baseline PTX ISA — compiles under compute_103)
// ---------------------------------------------------------------------------
__device__ __forceinline__ void ldsm_x4(uint32_t& r0, uint32_t& r1, uint32_t& r2, uint32_t& r3,
                                        uint32_t addr) {
    asm volatile("ldmatrix.sync.aligned.m8n8.x4.shared.b16 {%0,%1,%2,%3}, [%4];"
                 : "=r"(r0), "=r"(r1), "=r"(r2), "=r"(r3) : "r"(addr));
}
__device__ __forceinline__ void ldsm_x4_t(uint32_t& r0, uint32_t& r1, uint32_t& r2, uint32_t& r3,
                                          uint32_t addr) {
    asm volatile("ldmatrix.sync.aligned.m8n8.x4.trans.shared.b16 {%0,%1,%2,%3}, [%4];"
                 : "=r"(r0), "=r"(r1), "=r"(r2), "=r"(r3) : "r"(addr));
}
__device__ __forceinline__ void mma_bf16(float* d, const uint32_t* a, const uint32_t* b) {
    asm volatile(
        "mma.sync.aligned.m16n8k16.row.col.f32.bf16.bf16.f32 "
        "{%0,%1,%2,%3}, {%4,%5,%6,%7}, {%8,%9}, {%0,%1,%2,%3};"
        : "+f"(d[0]), "+f"(d[1]), "+f"(d[2]), "+f"(d[3])
        : "r"(a[0]), "r"(a[1]), "r"(a[2]), "r"(a[3]), "r"(b[0]), "r"(b[1]));
}
__device__ __forceinline__ uint32_t packbf(float a, float b) {
    __nv_bfloat162 t = __floats2bfloat162_rn(a, b);
    return *(uint32_t*)&t;
}
__device__ __forceinline__ void cp_async16(uint32_t saddr, const void* gptr) {
    asm volatile("cp.async.cg.shared.global [%0], [%1], 16;" :: "r"(saddr), "l"(gptr));
}
#define CP_COMMIT() asm volatile("cp.async.commit_group;" ::: "memory")
#define CP_WAIT1()  asm volatile("cp.async.wait_group 1;" ::: "memory")
#define CP_WAIT0()  asm volatile("cp.async.wait_group 0;" ::: "memory")

// ---------------------------------------------------------------------------
// Split fp32 -> (bf16 hi, bf16 lo). One thread per 4 elems.
// ---------------------------------------------------------------------------
__global__ void split_kernel(const float* __restrict__ x,
                             __nv_bfloat16* __restrict__ hi, __nv_bfloat16* __restrict__ lo)
{
    size_t i = ((size_t)blockIdx.x * blockDim.x + threadIdx.x) * 4;
    float4 v = *(const float4*)(x + i);
    float a[4] = {v.x, v.y, v.z, v.w};
    __nv_bfloat16 h[4], l[4];
#pragma unroll
    for (int j = 0; j < 4; ++j) {
        h[j] = __float2bfloat16(a[j]);
        l[j] = __float2bfloat16(a[j] - __bfloat162float(h[j]));
    }
    *(__nv_bfloat162*)(hi + i)     = __nv_bfloat162(h[0], h[1]);
    *(__nv_bfloat162*)(hi + i + 2) = __nv_bfloat162(h[2], h[3]);
    *(__nv_bfloat162*)(lo + i)     = __nv_bfloat162(l[0], l[1]);
    *(__nv_bfloat162*)(lo + i + 2) = __nv_bfloat162(l[2], l[3]);
}

// Tiled transpose + split: w [1024, N] -> wT hi/lo [N, 1024]. Coalesced both ways.
__global__ void splitT_kernel(const float* __restrict__ w,
                              __nv_bfloat16* __restrict__ hi, __nv_bfloat16* __restrict__ lo, int N)
{
    __shared__ float tile[32][33];
    const int bn = blockIdx.x * 32;
    const int bk = blockIdx.y * 32;
    const int tx = threadIdx.x;
    const int ty = threadIdx.y;
#pragma unroll
    for (int p = 0; p < 4; ++p)
        tile[ty + p * 8][tx] = w[(size_t)(bk + ty + p * 8) * N + bn + tx];
    __syncthreads();
#pragma unroll
    for (int p = 0; p < 4; ++p) {
        int n = bn + ty + p * 8;
        int k = bk + tx;
        float v = tile[tx][ty + p * 8];
        __nv_bfloat16 h = __float2bfloat16(v);
        hi[(size_t)n * 1024 + k] = h;
        lo[(size_t)n * 1024 + k] = __float2bfloat16(v - __bfloat162float(h));
    }
}

// ---------------------------------------------------------------------------
// GEMM: CTA 128x128, 8 warps 2x4, K-chunk 32, 3-stage cp.async pipeline,
// ONE barrier per chunk. SW64 swizzle (64B rows). Stage = 32KB.
// ---------------------------------------------------------------------------
#define GEMM_SMEM 98304

#define GEMM_PREFETCH(kc, st)                                                 \
    { const uint32_t sb_ = sbase + (st) * 32768;                              \
      _Pragma("unroll")                                                       \
      for (int p = 0; p < 2; ++p) {                                           \
          int idx = tid + p * 256;                                            \
          int r = idx >> 2, c = idx & 3;                                      \
          uint32_t so = SWZ64((uint32_t)(r * 64 + c * 16));                   \
          size_t goA = (size_t)(m0 + r) * 1024 + (kc) * 32 + c * 8;           \
          size_t goB = (size_t)(n0 + r) * 1024 + (kc) * 32 + c * 8;           \
          cp_async16(sb_ + 0     + so, Ahi + goA);                            \
          cp_async16(sb_ + 8192  + so, Alo + goA);                            \
          cp_async16(sb_ + 16384 + so, Bhi + goB);                            \
          cp_async16(sb_ + 24576 + so, Blo + goB);                            \
      } }

// Loop invariant: group g carries data for chunk g. At iteration kc, groups
// 0..kc+1 are committed; WAIT1 completes group kc; the barrier then (a) makes
// stage kc%3 visible to all warps and (b) seals compute kc-1 on stage
// (kc-1)%3 == (kc+2)%3 before this iteration's prefetch overwrites it.
#define GEMM_MAINLOOP(Ahi, Alo, Bhi, Blo)                                                 \
    GEMM_PREFETCH(0, 0); CP_COMMIT();                                                     \
    GEMM_PREFETCH(1, 1); CP_COMMIT();                                                     \
    for (int kc = 0; kc < 32; ++kc) {                                                     \
        CP_WAIT1();                                                                       \
        __syncthreads();                                                                  \
        if (kc + 2 < 32) { GEMM_PREFETCH(kc + 2, (kc + 2) % 3); }                         \
        CP_COMMIT();                                                                      \
        const uint32_t sb = sbase + (kc % 3) * 32768;                                     \
        _Pragma("unroll")                                                                 \
        for (int ks = 0; ks < 2; ++ks) {                                                  \
            const int kb = ks * 32;                                                       \
            uint32_t aoff[4], boff[2];                                                    \
            _Pragma("unroll")                                                             \
            for (int i = 0; i < 4; ++i) {                                                 \
                int row = wm * 64 + i * 16 + a_row_in;                                    \
                aoff[i] = SWZ64((uint32_t)(row * 64 + kb + a_kb));                        \
            }                                                                             \
            _Pragma("unroll")                                                             \
            for (int jp = 0; jp < 2; ++jp) {                                              \
                int row = wn * 32 + (jp * 2 + b_j2) * 8 + b_row_in;                       \
                boff[jp] = SWZ64((uint32_t)(row * 64 + kb + b_kb));                       \
            }                                                                             \
            uint32_t ah[4][4], al[4][4], bh[4][2], bl[4][2];                              \
            _Pragma("unroll")                                                             \
            for (int i = 0; i < 4; ++i) {                                                 \
                ldsm_x4(ah[i][0], ah[i][1], ah[i][2], ah[i][3], sb + 0    + aoff[i]);     \
                ldsm_x4(al[i][0], al[i][1], al[i][2], al[i][3], sb + 8192 + aoff[i]);     \
            }                                                                             \
            _Pragma("unroll")                                                             \
            for (int jp = 0; jp < 2; ++jp) {                                              \
                ldsm_x4(bh[jp * 2][0], bh[jp * 2][1], bh[jp * 2 + 1][0], bh[jp * 2 + 1][1],\
                        sb + 16384 + boff[jp]);                                           \
                ldsm_x4(bl[jp * 2][0], bl[jp * 2][1], bl[jp * 2 + 1][0], bl[jp * 2 + 1][1],\
                        sb + 24576 + boff[jp]);                                           \
            }                                                                             \
            _Pragma("unroll")                                                             \
            for (int i = 0; i < 4; ++i)                                                   \
                _Pragma("unroll")                                                         \
                for (int j = 0; j < 4; ++j) {                                             \
                    mma_bf16(acc[i][j], ah[i], bh[j]);                                    \
                    mma_bf16(acc[i][j], ah[i], bl[j]);                                    \
                    mma_bf16(acc[i][j], al[i], bh[j]);                                    \
                }                                                                         \
        }                                                                                 \
    }

#define GEMM_PROLOGUE()                                          \
    extern __shared__ char smem[];                               \
    const uint32_t sbase = (uint32_t)__cvta_generic_to_shared(smem); \
    const int tid = threadIdx.x;                                 \
    const int w = tid >> 5;                                      \
    const int l = tid & 31;                                      \
    const int wm = w >> 2;                                       \
    const int wn = w & 3;                                        \
    const int m0 = blockIdx.y * 128;                             \
    const int n0 = blockIdx.x * 128;                             \
    const int sub = l >> 3;                                      \
    const int a_row_in = ((sub & 1) << 3) + (l & 7);             \
    const int a_kb = (sub >> 1) << 4;                            \
    const int b_j2 = l >> 4;                                     \
    const int b_kb = ((l >> 3) & 1) << 4;                        \
    const int b_row_in = l & 7;                                  \
    float acc[4][4][4];                                          \
    _Pragma("unroll")                                            \
    for (int i = 0; i < 4; ++i)                                  \
        _Pragma("unroll")                                        \
        for (int j = 0; j < 4; ++j)                              \
            _Pragma("unroll")                                    \
            for (int r = 0; r < 4; ++r) acc[i][j][r] = 0.0f;

// ---------------------------------------------------------------------------
// QKV GEMM: epilogue scatters bf16 hi/lo splits into q/k/v (q pre-scaled).
// ---------------------------------------------------------------------------
__global__ void __launch_bounds__(256, 2) qkv_gemm(
    const __nv_bfloat16* __restrict__ Ahi, const __nv_bfloat16* __restrict__ Alo,
    const __nv_bfloat16* __restrict__ Bhi, const __nv_bfloat16* __restrict__ Blo,
    const float* __restrict__ bias,
    __nv_bfloat16* __restrict__ qhi, __nv_bfloat16* __restrict__ qlo,
    __nv_bfloat16* __restrict__ khi, __nv_bfloat16* __restrict__ klo,
    __nv_bfloat16* __restrict__ vhi, __nv_bfloat16* __restrict__ vlo)
{
    GEMM_PROLOGUE();
    GEMM_MAINLOOP(Ahi, Alo, Bhi, Blo);

    const int gr = l >> 2;
    const int gc = (l & 3) << 1;
#pragma unroll
    for (int i = 0; i < 4; ++i) {
        int mrow = m0 + wm * 64 + i * 16 + gr;
        int bb = mrow >> 11;
        int t = mrow & 2047;
#pragma unroll
        for (int j = 0; j < 4; ++j) {
            int n = n0 + wn * 32 + j * 8 + gc;
            int which = n >> 10;
            int c = n & 1023;
            int h = c >> 6;
            int d = c & 63;
            float2 bv = *(const float2*)(bias + n);
            float sc = (which == 0) ? KSCALE : 1.0f;
            __nv_bfloat16 *dhi, *dlo;
            if (which == 0)      { dhi = qhi; dlo = qlo; }
            else if (which == 1) { dhi = khi; dlo = klo; }
            else                 { dhi = vhi; dlo = vlo; }
            size_t off = (((size_t)bb * HH + h) * TT + t) * HD + d;
#pragma unroll
            for (int rr = 0; rr < 2; ++rr) {   // rows t and t+8
                float v0 = (acc[i][j][rr * 2 + 0] + bv.x) * sc;
                float v1 = (acc[i][j][rr * 2 + 1] + bv.y) * sc;
                __nv_bfloat162 hh = __floats2bfloat162_rn(v0, v1);
                float2 hf = __bfloat1622float2(hh);
                __nv_bfloat162 ll = __floats2bfloat162_rn(v0 - hf.x, v1 - hf.y);
                *(__nv_bfloat162*)(dhi + off + rr * 8 * HD) = hh;
                *(__nv_bfloat162*)(dlo + off + rr * 8 * HD) = ll;
            }
        }
    }
}

// ---------------------------------------------------------------------------
// Output projection: y(split) x w_out^T(split) + b_out -> fp32 out
// ---------------------------------------------------------------------------
__global__ void __launch_bounds__(256, 2) out_gemm(
    const __nv_bfloat16* __restrict__ Ahi, const __nv_bfloat16* __restrict__ Alo,
    const __nv_bfloat16* __restrict__ Bhi, const __nv_bfloat16* __restrict__ Blo,
    const float* __restrict__ bias, float* __restrict__ C0)
{
    GEMM_PROLOGUE();
    GEMM_MAINLOOP(Ahi, Alo, Bhi, Blo);

    const int gr = l >> 2;
    const int gc = (l & 3) << 1;
#pragma unroll
    for (int i = 0; i < 4; ++i) {
        int mrow = m0 + wm * 64 + i * 16 + gr;
#pragma unroll
        for (int j = 0; j < 4; ++j) {
            int n = n0 + wn * 32 + j * 8 + gc;
            float2 bv = *(const float2*)(bias + n);
            float* ptr = C0 + (size_t)mrow * DD + n;
            float2 v0, v1;
            v0.x = acc[i][j][0] + bv.x;
            v0.y = acc[i][j][1] + bv.y;
            v1.x = acc[i][j][2] + bv.x;
            v1.y = acc[i][j][3] + bv.y;
            *(float2*)ptr = v0;
            *(float2*)(ptr + 8 * DD) = v1;
        }
    }
}

// ---------------------------------------------------------------------------
// Tensor-core flash attention. CTA = 8 warps, q-tile 128 rows, k-tile 64 keys.
// 3-stage cp.async K/V pipeline, ONE barrier per k-tile. Q staged in stage 2.
// Reversed qt ordering (largest causal workload launches first).
// ---------------------------------------------------------------------------
#define ATT_SMEM 98304

#define FA_PREFETCH(kt, st)                                                   \
    { const uint32_t sb_ = sbase + (st) * 32768;                              \
      _Pragma("unroll")                                                       \
      for (int p = 0; p < 2; ++p) {                                           \
          int idx = tid + p * 256;                                            \
          int r = idx >> 3, c = idx & 7;                                      \
          uint32_t so = SWZ128((uint32_t)(r * 128 + c * 16));                 \
          size_t go = base + (size_t)((kt) * 64 + r) * HD + c * 8;            \
          cp_async16(sb_ + 0     + so, khi + go);                             \
          cp_async16(sb_ + 8192  + so, klo + go);                             \
          cp_async16(sb_ + 16384 + so, vhi + go);                             \
          cp_async16(sb_ + 24576 + so, vlo + go);                             \
      } }

__global__ void __launch_bounds__(256) fa_kernel(
    const __nv_bfloat16* __restrict__ qhi, const __nv_bfloat16* __restrict__ qlo,
    const __nv_bfloat16* __restrict__ khi, const __nv_bfloat16* __restrict__ klo,
    const __nv_bfloat16* __restrict__ vhi, const __nv_bfloat16* __restrict__ vlo,
    __nv_bfloat16* __restrict__ yhi, __nv_bfloat16* __restrict__ ylo)
{
    extern __shared__ char smem[];
    const uint32_t sbase = (uint32_t)__cvta_generic_to_shared(smem);
    const int tid = threadIdx.x;
    const int w = tid >> 5;          // 0..7 -> q rows w*16..w*16+15
    const int l = tid & 31;
    const int qtv = (TT / 128 - 1) - blockIdx.x;   // reversed: big tiles first
    const int bhid = blockIdx.y;
    const int q0 = qtv * 128;
    const int kt_max = 2 * qtv + 1;
    const size_t base = (size_t)bhid * TT * HD;

    // A-fragment lane mapping
    const int sub = l >> 3;
    const int a_row_in = ((sub & 1) << 3) + (l & 7);
    const int a_kb = (sub >> 1) << 4;
    // B-fragment (non-trans, K) lane mapping
    const int b_j2 = l >> 4;
    const int b_kb = ((l >> 3) & 1) << 4;
    const int b_row_in = l & 7;
    // B-fragment (trans, V) lane mapping
    const int v_key_in = (l & 7) + ((l >> 3) & 1) * 8;
    const int v_n16 = l >> 4;

    // ---- stage Q tile (128 rows, hi/lo) into stage-2 region ----
#pragma unroll
    for (int p = 0; p < 4; ++p) {
        int idx = tid + p * 256;
        int r = idx >> 3;
        int c = idx & 7;
        uint32_t so = SWZ128((uint32_t)(r * 128 + c * 16));
        size_t go = base + (size_t)(q0 + r) * HD + c * 8;
        *(uint4*)(smem + 65536 + 0     + so) = *(const uint4*)(qhi + go);
        *(uint4*)(smem + 65536 + 16384 + so) = *(const uint4*)(qlo + go);
    }
    // prefetch kt=0,1 into stages 0,1 (commit both; group g = k-tile g data)
    FA_PREFETCH(0, 0); CP_COMMIT();
    FA_PREFETCH(1, 1); CP_COMMIT();
    __syncthreads();

    uint32_t qh[4][4], ql[4][4];
#pragma unroll
    for (int ks = 0; ks < 4; ++ks) {
        uint32_t off = SWZ128((uint32_t)((w * 16 + a_row_in) * 128 + ks * 32 + a_kb));
        ldsm_x4(qh[ks][0], qh[ks][1], qh[ks][2], qh[ks][3], sbase + 65536 + 0     + off);
        ldsm_x4(ql[ks][0], ql[ks][1], ql[ks][2], ql[ks][3], sbase + 65536 + 16384 + off);
    }

    float o[8][4];
#pragma unroll
    for (int j = 0; j < 8; ++j)
#pragma unroll
        for (int r = 0; r < 4; ++r) o[j][r] = 0.0f;
    float m0r = -CUDART_INF_F, m1r = -CUDART_INF_F;
    float l0r = 0.0f, l1r = 0.0f;

    const int rloc0 = w * 16 + (l >> 2);
    const int tq0 = q0 + rloc0;            // global q rows tq0, tq0+8

    for (int kt = 0; kt <= kt_max; ++kt) {
        // groups 0..kt+1 committed; WAIT1 completes group kt; barrier makes
        // stage kt%3 visible and seals compute kt-1 (incl. Q-frag reads of
        // stage 2 before the first overwrite) before the prefetch below.
        CP_WAIT1();
        __syncthreads();
        if (kt + 2 <= kt_max) { FA_PREFETCH(kt + 2, (kt + 2) % 3); }
        CP_COMMIT();
        const uint32_t sb = sbase + (kt % 3) * 32768;
        const int k0 = kt * 64;

        // ---- S = Q K^T (3-term), fp32 accum ----
        float s[8][4];
#pragma unroll
        for (int j = 0; j < 8; ++j)
#pragma unroll
            for (int r = 0; r < 4; ++r) s[j][r] = 0.0f;

#pragma unroll
        for (int ks = 0; ks < 4; ++ks) {
            uint32_t kbh[8][2], kbl[8][2];
#pragma unroll
            for (int jp = 0; jp < 4; ++jp) {
                int row = (jp * 2 + b_j2) * 8 + b_row_in;
                uint32_t off = SWZ128((uint32_t)(row * 128 + ks * 32 + b_kb));
                ldsm_x4(kbh[jp * 2][0], kbh[jp * 2][1], kbh[jp * 2 + 1][0], kbh[jp * 2 + 1][1],
                        sb + 0 + off);
                ldsm_x4(kbl[jp * 2][0], kbl[jp * 2][1], kbl[jp * 2 + 1][0], kbl[jp * 2 + 1][1],
                        sb + 8192 + off);
            }
#pragma unroll
            for (int j = 0; j < 8; ++j) {
                mma_bf16(s[j], qh[ks], kbh[j]);
                mma_bf16(s[j], qh[ks], kbl[j]);
                mma_bf16(s[j], ql[ks], kbh[j]);
            }
        }

        // ---- causal mask (diagonal spans the last two k-tiles) ----
        if (kt >= 2 * qtv) {
#pragma unroll
            for (int j = 0; j < 8; ++j) {
                int gcol = k0 + j * 8 + ((l & 3) << 1);
                if (gcol > tq0)         s[j][0] = -CUDART_INF_F;
                if (gcol + 1 > tq0)     s[j][1] = -CUDART_INF_F;
                if (gcol > tq0 + 8)     s[j][2] = -CUDART_INF_F;
                if (gcol + 1 > tq0 + 8) s[j][3] = -CUDART_INF_F;
            }
        }

        // ---- online softmax (rows tq0, tq0+8) ----
        float mx0 = -CUDART_INF_F, mx1 = -CUDART_INF_F;
#pragma unroll
        for (int j = 0; j < 8; ++j) {
            mx0 = fmaxf(mx0, fmaxf(s[j][0], s[j][1]));
            mx1 = fmaxf(mx1, fmaxf(s[j][2], s[j][3]));
        }
        mx0 = fmaxf(mx0, __shfl_xor_sync(0xffffffffu, mx0, 1));
        mx0 = fmaxf(mx0, __shfl_xor_sync(0xffffffffu, mx0, 2));
        mx1 = fmaxf(mx1, __shfl_xor_sync(0xffffffffu, mx1, 1));
        mx1 = fmaxf(mx1, __shfl_xor_sync(0xffffffffu, mx1, 2));

        float mn0 = fmaxf(m0r, mx0);
        float mn1 = fmaxf(m1r, mx1);
        float al0 = exp2f(m0r - mn0);
        float al1 = exp2f(m1r - mn1);
        m0r = mn0; m1r = mn1;

        float rs0 = 0.0f, rs1 = 0.0f;
#pragma unroll
        for (int j = 0; j < 8; ++j) {
            s[j][0] = exp2f(s[j][0] - mn0);
            s[j][1] = exp2f(s[j][1] - mn0);
            s[j][2] = exp2f(s[j][2] - mn1);
            s[j][3] = exp2f(s[j][3] - mn1);
            rs0 += s[j][0] + s[j][1];
            rs1 += s[j][2] + s[j][3];
        }
        rs0 += __shfl_xor_sync(0xffffffffu, rs0, 1);
        rs0 += __shfl_xor_sync(0xffffffffu, rs0, 2);
        rs1 += __shfl_xor_sync(0xffffffffu, rs1, 1);
        rs1 += __shfl_xor_sync(0xffffffffu, rs1, 2);
        l0r = l0r * al0 + rs0;
        l1r = l1r * al1 + rs1;

#pragma unroll
        for (int j = 0; j < 8; ++j) {
            o[j][0] *= al0; o[j][1] *= al0;
            o[j][2] *= al1; o[j][3] *= al1;
        }

        // ---- pack P into bf16 hi/lo A fragments (C layout == A layout) ----
        uint32_t ph[4][4], pl[4][4];
#pragma unroll
        for (int t = 0; t < 4; ++t) {
            const float* s0 = s[2 * t];
            const float* s1 = s[2 * t + 1];
            float2 hf;
            ph[t][0] = packbf(s0[0], s0[1]);
            hf = __bfloat1622float2(*(__nv_bfloat162*)&ph[t][0]);
            pl[t][0] = packbf(s0[0] - hf.x, s0[1] - hf.y);
            ph[t][1] = packbf(s0[2], s0[3]);
            hf = __bfloat1622float2(*(__nv_bfloat162*)&ph[t][1]);
            pl[t][1] = packbf(s0[2] - hf.x, s0[3] - hf.y);
            ph[t][2] = packbf(s1[0], s1[1]);
            hf = __bfloat1622float2(*(__nv_bfloat162*)&ph[t][2]);
            pl[t][2] = packbf(s1[0] - hf.x, s1[1] - hf.y);
            ph[t][3] = packbf(s1[2], s1[3]);
            hf = __bfloat1622float2(*(__nv_bfloat162*)&ph[t][3]);
            pl[t][3] = packbf(s1[2] - hf.x, s1[3] - hf.y);
        }

        // ---- O += P @ V (3-term), V^T fragments via ldmatrix.trans ----
#pragma unroll
        for (int t = 0; t < 4; ++t) {
            uint32_t vbh[8][2], vbl[8][2];
#pragma unroll
            for (int jp = 0; jp < 4; ++jp) {
                int key = t * 16 + v_key_in;
                int n16 = jp * 2 + v_n16;
                uint32_t off = SWZ128((uint32_t)(key * 128 + n16 * 16));
                ldsm_x4_t(vbh[jp * 2][0], vbh[jp * 2][1], vbh[jp * 2 + 1][0], vbh[jp * 2 + 1][1],
                          sb + 16384 + off);
                ldsm_x4_t(vbl[jp * 2][0], vbl[jp * 2][1], vbl[jp * 2 + 1][0], vbl[jp * 2 + 1][1],
                          sb + 24576 + off);
            }
#pragma unroll
            for (int j = 0; j < 8; ++j) {
                mma_bf16(o[j], ph[t], vbh[j]);
                mma_bf16(o[j], ph[t], vbl[j]);
                mma_bf16(o[j], pl[t], vbh[j]);
            }
        }
    }

    // ---- epilogue: normalize, split to bf16 hi/lo, store y[B,T,D] ----
    const int b = bhid >> 4;
    const int h = bhid & 15;
    const float inv0 = 1.0f / l0r;
    const float inv1 = 1.0f / l1r;
#pragma unroll
    for (int j = 0; j < 8; ++j) {
        int col = h * 64 + j * 8 + ((l & 3) << 1);
        size_t off0 = ((size_t)b * TT + tq0) * DD + col;
        size_t off1 = ((size_t)b * TT + tq0 + 8) * DD + col;
        float v0 = o[j][0] * inv0, v1 = o[j][1] * inv0;
        float v2 = o[j][2] * inv1, v3 = o[j][3] * inv1;
        __nv_bfloat162 h0 = __floats2bfloat162_rn(v0, v1);
        float2 hf0 = __bfloat1622float2(h0);
        __nv_bfloat162 l0 = __floats2bfloat162_rn(v0 - hf0.x, v1 - hf0.y);
        __nv_bfloat162 h1 = __floats2bfloat162_rn(v2, v3);
        float2 hf1 = __bfloat1622float2(h1);
        __nv_bfloat162 l1 = __floats2bfloat162_rn(v2 - hf1.x, v3 - hf1.y);
        *(__nv_bfloat162*)(yhi + off0) = h0;
        *(__nv_bfloat162*)(ylo + off0) = l0;
        *(__nv_bfloat162*)(yhi + off1) = h1;
        *(__nv_bfloat162*)(ylo + off1) = l1;
    }
}

// ---------------------------------------------------------------------------
// Launch pipeline
// ---------------------------------------------------------------------------
extern "C" void kernel_launch(void* const* d_in, const int* in_sizes, int n_in,
                              void* d_out, int out_size)
{
    (void)in_sizes; (void)n_in; (void)out_size;
    const float* x     = (const float*)d_in[0];
    // d_in[1] = causal mask, handled analytically
    const float* w_qkv = (const float*)d_in[2];
    const float* b_qkv = (const float*)d_in[3];
    const float* w_out = (const float*)d_in[4];
    const float* b_out = (const float*)d_in[5];
    float* out = (float*)d_out;

    __nv_bfloat16 *qhi, *qlo, *khi, *klo, *vhi, *vlo;
    __nv_bfloat16 *xhi, *xlo, *wqhi, *wqlo, *wohi, *wolo, *yhi, *ylo;
    cudaGetSymbolAddress((void**)&qhi, g_qhi);
    cudaGetSymbolAddress((void**)&qlo, g_qlo);
    cudaGetSymbolAddress((void**)&khi, g_khi);
    cudaGetSymbolAddress((void**)&klo, g_klo);
    cudaGetSymbolAddress((void**)&vhi, g_vhi);
    cudaGetSymbolAddress((void**)&vlo, g_vlo);
    cudaGetSymbolAddress((void**)&xhi, g_xhi);
    cudaGetSymbolAddress((void**)&xlo, g_xlo);
    cudaGetSymbolAddress((void**)&wqhi, g_wqhi);
    cudaGetSymbolAddress((void**)&wqlo, g_wqlo);
    cudaGetSymbolAddress((void**)&wohi, g_wohi);
    cudaGetSymbolAddress((void**)&wolo, g_wolo);
    cudaGetSymbolAddress((void**)&yhi, g_yhi);
    cudaGetSymbolAddress((void**)&ylo, g_ylo);

    cudaFuncSetAttribute(qkv_gemm, cudaFuncAttributeMaxDynamicSharedMemorySize, GEMM_SMEM);
    cudaFuncSetAttribute(out_gemm, cudaFuncAttributeMaxDynamicSharedMemorySize, GEMM_SMEM);
    cudaFuncSetAttribute(fa_kernel, cudaFuncAttributeMaxDynamicSharedMemorySize, ATT_SMEM);

    const size_t MX = (size_t)BB * TT * DD;  // 8388608

    split_kernel<<<(unsigned)(MX / 4 / 256), 256>>>(x, xhi, xlo);
    {
        dim3 grid(3 * DD / 32, DD / 32);
        splitT_kernel<<<grid, dim3(32, 8)>>>(w_qkv, wqhi, wqlo, 3 * DD);
    }
    {
        dim3 grid(DD / 32, DD / 32);
        splitT_kernel<<<grid, dim3(32, 8)>>>(w_out, wohi, wolo, DD);
    }

    // 1) QKV projection -> bf16 hi/lo q/k/v, [B,H,T,HD], q pre-scaled
    {
        dim3 grid(3 * DD / 128, BB * TT / 128);   // (24, 64)
        qkv_gemm<<<grid, 256, GEMM_SMEM>>>(xhi, xlo, wqhi, wqlo, b_qkv,
                                           qhi, qlo, khi, klo, vhi, vlo);
    }

    // 2) tensor-core causal flash attention -> y bf16 hi/lo
    {
        dim3 grid(TT / 128, BB * HH);             // (16, 64), qt reversed in-kernel
        fa_kernel<<<grid, 256, ATT_SMEM>>>(qhi, qlo, khi, klo, vhi, vlo, yhi, ylo);
    }

    // 3) output projection -> fp32 out
    {
        dim3 grid(DD / 128, BB * TT / 128);       // (8, 64)
        out_gemm<<<grid, 256, GEMM_SMEM>>>(yhi, ylo, wohi, wolo, b_out, out);
    }
}

// round 7
// speedup vs baseline: 1.5107x; 1.5107x over previous
#include <cuda_runtime.h>
#include <cuda_fp16.h>
#include <math_constants.h>
#include <cstddef>
#include <cstdint>

// Problem constants
#define BB 4
#define TT 2048
#define DD 1024
#define HH 16
#define HD 64

#define KSCALE (0.125f * 1.4426950408889634f)   // 1/sqrt(64) * log2(e)

// ---------------------------------------------------------------------------
// Scratch (device globals: allocation-guard-safe)
// A-side operands are fp16 hi/lo split; B-side operands are single fp16.
// ---------------------------------------------------------------------------
__device__ __half g_qhi[(size_t)BB * HH * TT * HD];  // [B,H,T,HD], pre-scaled
__device__ __half g_qlo[(size_t)BB * HH * TT * HD];
__device__ __half g_kh [(size_t)BB * HH * TT * HD];
__device__ __half g_vh [(size_t)BB * HH * TT * HD];

__device__ __half g_xhi[(size_t)BB * TT * DD];
__device__ __half g_xlo[(size_t)BB * TT * DD];
__device__ __half g_wqh[(size_t)3 * DD * DD];        // w_qkv^T [3072,1024]
__device__ __half g_woh[(size_t)DD * DD];            // w_out^T [1024,1024]
__device__ __half g_yhi[(size_t)BB * TT * DD];       // attention out, split
__device__ __half g_ylo[(size_t)BB * TT * DD];

#define SWZ128(o) ((o) ^ (((o) >> 3) & 0x70))
#define SWZ64(o)  ((o) ^ (((o) >> 3) & 0x30))

// ---------------------------------------------------------------------------
// mma.sync / cp.async helpers (baseline PTX ISA — compiles under compute_103)
// ---------------------------------------------------------------------------
__device__ __forceinline__ void ldsm_x4(uint32_t& r0, uint32_t& r1, uint32_t& r2, uint32_t& r3,
                                        uint32_t addr) {
    asm volatile("ldmatrix.sync.aligned.m8n8.x4.shared.b16 {%0,%1,%2,%3}, [%4];"
                 : "=r"(r0), "=r"(r1), "=r"(r2), "=r"(r3) : "r"(addr));
}
__device__ __forceinline__ void ldsm_x4_t(uint32_t& r0, uint32_t& r1, uint32_t& r2, uint32_t& r3,
                                          uint32_t addr) {
    asm volatile("ldmatrix.sync.aligned.m8n8.x4.trans.shared.b16 {%0,%1,%2,%3}, [%4];"
                 : "=r"(r0), "=r"(r1), "=r"(r2), "=r"(r3) : "r"(addr));
}
__device__ __forceinline__ void mma_f16(float* d, const uint32_t* a, const uint32_t* b) {
    asm volatile(
        "mma.sync.aligned.m16n8k16.row.col.f32.f16.f16.f32 "
        "{%0,%1,%2,%3}, {%4,%5,%6,%7}, {%8,%9}, {%0,%1,%2,%3};"
        : "+f"(d[0]), "+f"(d[1]), "+f"(d[2]), "+f"(d[3])
        : "r"(a[0]), "r"(a[1]), "r"(a[2]), "r"(a[3]), "r"(b[0]), "r"(b[1]));
}
__device__ __forceinline__ uint32_t packh(float a, float b) {
    __half2 t = __floats2half2_rn(a, b);
    return *(uint32_t*)&t;
}
__device__ __forceinline__ void cp_async16(uint32_t saddr, const void* gptr) {
    asm volatile("cp.async.cg.shared.global [%0], [%1], 16;" :: "r"(saddr), "l"(gptr));
}
#define CP_COMMIT() asm volatile("cp.async.commit_group;" ::: "memory")
#define CP_WAIT1()  asm volatile("cp.async.wait_group 1;" ::: "memory")
#define CP_WAIT0()  asm volatile("cp.async.wait_group 0;" ::: "memory")

// ---------------------------------------------------------------------------
// Split fp32 -> (fp16 hi, fp16 lo). One thread per 4 elems.
// ---------------------------------------------------------------------------
__global__ void split_kernel(const float* __restrict__ x,
                             __half* __restrict__ hi, __half* __restrict__ lo)
{
    size_t i = ((size_t)blockIdx.x * blockDim.x + threadIdx.x) * 4;
    float4 v = *(const float4*)(x + i);
    float a[4] = {v.x, v.y, v.z, v.w};
    __half h[4], l[4];
#pragma unroll
    for (int j = 0; j < 4; ++j) {
        h[j] = __float2half_rn(a[j]);
        l[j] = __float2half_rn(a[j] - __half2float(h[j]));
    }
    *(__half2*)(hi + i)     = __halves2half2(h[0], h[1]);
    *(__half2*)(hi + i + 2) = __halves2half2(h[2], h[3]);
    *(__half2*)(lo + i)     = __halves2half2(l[0], l[1]);
    *(__half2*)(lo + i + 2) = __halves2half2(l[2], l[3]);
}

// Tiled transpose to single fp16: w [1024, N] -> wT [N, 1024].
__global__ void splitT_kernel(const float* __restrict__ w,
                              __half* __restrict__ hi, int N)
{
    __shared__ float tile[32][33];
    const int bn = blockIdx.x * 32;
    const int bk = blockIdx.y * 32;
    const int tx = threadIdx.x;
    const int ty = threadIdx.y;
#pragma unroll
    for (int p = 0; p < 4; ++p)
        tile[ty + p * 8][tx] = w[(size_t)(bk + ty + p * 8) * N + bn + tx];
    __syncthreads();
#pragma unroll
    for (int p = 0; p < 4; ++p) {
        int n = bn + ty + p * 8;
        int k = bk + tx;
        hi[(size_t)n * 1024 + k] = __float2half_rn(tile[tx][ty + p * 8]);
    }
}

// ---------------------------------------------------------------------------
// GEMM: CTA 128x128, 8 warps 2x4, K-chunk 32, 2-stage cp.async pipeline,
// SW64 swizzle (64B rows). Stage = 24KB: [AHI 8K | ALO 8K | BH 8K].
// A-side fp16 2-term split, B-side single fp16: 2 MMAs per (i,j,k16).
// ---------------------------------------------------------------------------
#define GST 24576
#define GEMM_SMEM 49152

#define GEMM_PREFETCH(kc, st)                                                 \
    { const uint32_t sb_ = sbase + (st) * GST;                                \
      _Pragma("unroll")                                                       \
      for (int p = 0; p < 2; ++p) {                                           \
          int idx = tid + p * 256;                                            \
          int r = idx >> 2, c = idx & 3;                                      \
          uint32_t so = SWZ64((uint32_t)(r * 64 + c * 16));                   \
          size_t goA = (size_t)(m0 + r) * 1024 + (kc) * 32 + c * 8;           \
          size_t goB = (size_t)(n0 + r) * 1024 + (kc) * 32 + c * 8;           \
          cp_async16(sb_ + 0     + so, Ahi + goA);                            \
          cp_async16(sb_ + 8192  + so, Alo + goA);                            \
          cp_async16(sb_ + 16384 + so, Bh + goB);                             \
      } }

#define GEMM_MAINLOOP(Ahi, Alo, Bh)                                                       \
    GEMM_PREFETCH(0, 0); CP_COMMIT();                                                     \
    for (int kc = 0; kc < 32; ++kc) {                                                     \
        if (kc + 1 < 32) { GEMM_PREFETCH(kc + 1, (kc + 1) & 1); CP_COMMIT(); CP_WAIT1(); }\
        else { CP_WAIT0(); }                                                              \
        __syncthreads();                                                                  \
        const uint32_t sb = sbase + (kc & 1) * GST;                                       \
        _Pragma("unroll")                                                                 \
        for (int ks = 0; ks < 2; ++ks) {                                                  \
            const int kb = ks * 32;                                                       \
            uint32_t aoff[4], boff[2];                                                    \
            _Pragma("unroll")                                                             \
            for (int i = 0; i < 4; ++i) {                                                 \
                int row = wm * 64 + i * 16 + a_row_in;                                    \
                aoff[i] = SWZ64((uint32_t)(row * 64 + kb + a_kb));                        \
            }                                                                             \
            _Pragma("unroll")                                                             \
            for (int jp = 0; jp < 2; ++jp) {                                              \
                int row = wn * 32 + (jp * 2 + b_j2) * 8 + b_row_in;                       \
                boff[jp] = SWZ64((uint32_t)(row * 64 + kb + b_kb));                       \
            }                                                                             \
            uint32_t ah[4][4], al[4][4], bh[4][2];                                        \
            _Pragma("unroll")                                                             \
            for (int i = 0; i < 4; ++i) {                                                 \
                ldsm_x4(ah[i][0], ah[i][1], ah[i][2], ah[i][3], sb + 0    + aoff[i]);     \
                ldsm_x4(al[i][0], al[i][1], al[i][2], al[i][3], sb + 8192 + aoff[i]);     \
            }                                                                             \
            _Pragma("unroll")                                                             \
            for (int jp = 0; jp < 2; ++jp)                                                \
                ldsm_x4(bh[jp * 2][0], bh[jp * 2][1], bh[jp * 2 + 1][0], bh[jp * 2 + 1][1],\
                        sb + 16384 + boff[jp]);                                           \
            _Pragma("unroll")                                                             \
            for (int i = 0; i < 4; ++i)                                                   \
                _Pragma("unroll")                                                         \
                for (int j = 0; j < 4; ++j) {                                             \
                    mma_f16(acc[i][j], ah[i], bh[j]);                                     \
                    mma_f16(acc[i][j], al[i], bh[j]);                                     \
                }                                                                         \
        }                                                                                 \
        __syncthreads();                                                                  \
    }

#define GEMM_PROLOGUE()                                          \
    extern __shared__ char smem[];                               \
    const uint32_t sbase = (uint32_t)__cvta_generic_to_shared(smem); \
    const int tid = threadIdx.x;                                 \
    const int w = tid >> 5;                                      \
    const int l = tid & 31;                                      \
    const int wm = w >> 2;                                       \
    const int wn = w & 3;                                        \
    const int m0 = blockIdx.y * 128;                             \
    const int n0 = blockIdx.x * 128;                             \
    const int sub = l >> 3;                                      \
    const int a_row_in = ((sub & 1) << 3) + (l & 7);             \
    const int a_kb = (sub >> 1) << 4;                            \
    const int b_j2 = l >> 4;                                     \
    const int b_kb = ((l >> 3) & 1) << 4;                        \
    const int b_row_in = l & 7;                                  \
    float acc[4][4][4];                                          \
    _Pragma("unroll")                                            \
    for (int i = 0; i < 4; ++i)                                  \
        _Pragma("unroll")                                        \
        for (int j = 0; j < 4; ++j)                              \
            _Pragma("unroll")                                    \
            for (int r = 0; r < 4; ++r) acc[i][j][r] = 0.0f;

// ---------------------------------------------------------------------------
// QKV GEMM: epilogue scatters q (fp16 hi/lo, pre-scaled) and k/v (single fp16).
// ---------------------------------------------------------------------------
__global__ void __launch_bounds__(256, 2) qkv_gemm(
    const __half* __restrict__ Ahi, const __half* __restrict__ Alo,
    const __half* __restrict__ Bh,
    const float* __restrict__ bias,
    __half* __restrict__ qhi, __half* __restrict__ qlo,
    __half* __restrict__ kh, __half* __restrict__ vh)
{
    GEMM_PROLOGUE();
    GEMM_MAINLOOP(Ahi, Alo, Bh);

    const int gr = l >> 2;
    const int gc = (l & 3) << 1;
#pragma unroll
    for (int i = 0; i < 4; ++i) {
        int mrow = m0 + wm * 64 + i * 16 + gr;
        int bb = mrow >> 11;
        int t = mrow & 2047;
#pragma unroll
        for (int j = 0; j < 4; ++j) {
            int n = n0 + wn * 32 + j * 8 + gc;
            int which = n >> 10;
            int c = n & 1023;
            int h = c >> 6;
            int d = c & 63;
            float2 bv = *(const float2*)(bias + n);
            size_t off = (((size_t)bb * HH + h) * TT + t) * HD + d;
#pragma unroll
            for (int rr = 0; rr < 2; ++rr) {   // rows t and t+8
                float v0 = acc[i][j][rr * 2 + 0] + bv.x;
                float v1 = acc[i][j][rr * 2 + 1] + bv.y;
                if (which == 0) {
                    v0 *= KSCALE; v1 *= KSCALE;
                    __half2 hh = __floats2half2_rn(v0, v1);
                    float2 hf = __half22float2(hh);
                    __half2 ll = __floats2half2_rn(v0 - hf.x, v1 - hf.y);
                    *(__half2*)(qhi + off + rr * 8 * HD) = hh;
                    *(__half2*)(qlo + off + rr * 8 * HD) = ll;
                } else {
                    __half* dst = (which == 1) ? kh : vh;
                    *(__half2*)(dst + off + rr * 8 * HD) = __floats2half2_rn(v0, v1);
                }
            }
        }
    }
}

// ---------------------------------------------------------------------------
// Output projection: y(split) x w_out^T(fp16) + b_out -> fp32 out
// ---------------------------------------------------------------------------
__global__ void __launch_bounds__(256, 2) out_gemm(
    const __half* __restrict__ Ahi, const __half* __restrict__ Alo,
    const __half* __restrict__ Bh,
    const float* __restrict__ bias, float* __restrict__ C0)
{
    GEMM_PROLOGUE();
    GEMM_MAINLOOP(Ahi, Alo, Bh);

    const int gr = l >> 2;
    const int gc = (l & 3) << 1;
#pragma unroll
    for (int i = 0; i < 4; ++i) {
        int mrow = m0 + wm * 64 + i * 16 + gr;
#pragma unroll
        for (int j = 0; j < 4; ++j) {
            int n = n0 + wn * 32 + j * 8 + gc;
            float2 bv = *(const float2*)(bias + n);
            float* ptr = C0 + (size_t)mrow * DD + n;
            float2 v0, v1;
            v0.x = acc[i][j][0] + bv.x;
            v0.y = acc[i][j][1] + bv.y;
            v1.x = acc[i][j][2] + bv.x;
            v1.y = acc[i][j][3] + bv.y;
            *(float2*)ptr = v0;
            *(float2*)(ptr + 8 * DD) = v1;
        }
    }
}

// ---------------------------------------------------------------------------
// Tensor-core flash attention, fp16 2-term. CTA = 4 warps, q-tile 64 rows,
// k-tile 64 keys, 2-stage cp.async K/V pipeline (stage 16KB: K 8K | V 8K).
// Q (hi/lo) staged in a dedicated region. Total smem 48KB.
// ---------------------------------------------------------------------------
#define FST 16384
#define ATT_SMEM 49152

#define FA_PREFETCH(kt, st)                                                   \
    { const uint32_t sb_ = sbase + (st) * FST;                                \
      _Pragma("unroll")                                                       \
      for (int p = 0; p < 4; ++p) {                                           \
          int idx = tid + p * 128;                                            \
          int r = idx >> 3, c = idx & 7;                                      \
          uint32_t so = SWZ128((uint32_t)(r * 128 + c * 16));                 \
          size_t go = base + (size_t)((kt) * 64 + r) * HD + c * 8;            \
          cp_async16(sb_ + 0    + so, kh + go);                               \
          cp_async16(sb_ + 8192 + so, vh + go);                               \
      } }

__global__ void __launch_bounds__(128) fa_kernel(
    const __half* __restrict__ qhi, const __half* __restrict__ qlo,
    const __half* __restrict__ kh, const __half* __restrict__ vh,
    __half* __restrict__ yhi, __half* __restrict__ ylo)
{
    extern __shared__ char smem[];
    const uint32_t sbase = (uint32_t)__cvta_generic_to_shared(smem);
    const int tid = threadIdx.x;
    const int w = tid >> 5;
    const int l = tid & 31;
    const int qt = blockIdx.x;
    const int bhid = blockIdx.y;
    const int q0 = qt * 64;
    const size_t base = (size_t)bhid * TT * HD;

    // A-fragment lane mapping
    const int sub = l >> 3;
    const int a_row_in = ((sub & 1) << 3) + (l & 7);
    const int a_kb = (sub >> 1) << 4;
    // B-fragment (non-trans, K) lane mapping
    const int b_j2 = l >> 4;
    const int b_kb = ((l >> 3) & 1) << 4;
    const int b_row_in = l & 7;
    // B-fragment (trans, V) lane mapping
    const int v_key_in = (l & 7) + ((l >> 3) & 1) * 8;
    const int v_n16 = l >> 4;

    // ---- stage Q tile (hi/lo) into dedicated region at +32768 ----
#pragma unroll
    for (int p = 0; p < 4; ++p) {
        int idx = tid + p * 128;
        int r = idx >> 3;
        int c = idx & 7;
        uint32_t so = SWZ128((uint32_t)(r * 128 + c * 16));
        size_t go = base + (size_t)(q0 + r) * HD + c * 8;
        *(uint4*)(smem + 32768 + 0    + so) = *(const uint4*)(qhi + go);
        *(uint4*)(smem + 32768 + 8192 + so) = *(const uint4*)(qlo + go);
    }
    FA_PREFETCH(0, 0); CP_COMMIT();
    __syncthreads();

    uint32_t qh[4][4], ql[4][4];
#pragma unroll
    for (int ks = 0; ks < 4; ++ks) {
        uint32_t off = SWZ128((uint32_t)((w * 16 + a_row_in) * 128 + ks * 32 + a_kb));
        ldsm_x4(qh[ks][0], qh[ks][1], qh[ks][2], qh[ks][3], sbase + 32768 + 0    + off);
        ldsm_x4(ql[ks][0], ql[ks][1], ql[ks][2], ql[ks][3], sbase + 32768 + 8192 + off);
    }

    float o[8][4];
#pragma unroll
    for (int j = 0; j < 8; ++j)
#pragma unroll
        for (int r = 0; r < 4; ++r) o[j][r] = 0.0f;
    float m0r = -CUDART_INF_F, m1r = -CUDART_INF_F;
    float l0r = 0.0f, l1r = 0.0f;

    const int rloc0 = w * 16 + (l >> 2);

    for (int kt = 0; kt <= qt; ++kt) {
        if (kt + 1 <= qt) { FA_PREFETCH(kt + 1, (kt + 1) & 1); CP_COMMIT(); CP_WAIT1(); }
        else { CP_WAIT0(); }
        __syncthreads();
        const uint32_t sb = sbase + (kt & 1) * FST;

        // ---- S = Q K^T (2-term fp16), fp32 accum ----
        float s[8][4];
#pragma unroll
        for (int j = 0; j < 8; ++j)
#pragma unroll
            for (int r = 0; r < 4; ++r) s[j][r] = 0.0f;

#pragma unroll
        for (int ks = 0; ks < 4; ++ks) {
            uint32_t kb[8][2];
#pragma unroll
            for (int jp = 0; jp < 4; ++jp) {
                int row = (jp * 2 + b_j2) * 8 + b_row_in;
                uint32_t off = SWZ128((uint32_t)(row * 128 + ks * 32 + b_kb));
                ldsm_x4(kb[jp * 2][0], kb[jp * 2][1], kb[jp * 2 + 1][0], kb[jp * 2 + 1][1],
                        sb + 0 + off);
            }
#pragma unroll
            for (int j = 0; j < 8; ++j) {
                mma_f16(s[j], qh[ks], kb[j]);
                mma_f16(s[j], ql[ks], kb[j]);
            }
        }

        // ---- causal mask on diagonal tile ----
        if (kt == qt) {
#pragma unroll
            for (int j = 0; j < 8; ++j) {
                int c = j * 8 + ((l & 3) << 1);
                if (c > rloc0)         s[j][0] = -CUDART_INF_F;
                if (c + 1 > rloc0)     s[j][1] = -CUDART_INF_F;
                if (c > rloc0 + 8)     s[j][2] = -CUDART_INF_F;
                if (c + 1 > rloc0 + 8) s[j][3] = -CUDART_INF_F;
            }
        }

        // ---- online softmax (rows rloc0, rloc0+8) ----
        float mx0 = -CUDART_INF_F, mx1 = -CUDART_INF_F;
#pragma unroll
        for (int j = 0; j < 8; ++j) {
            mx0 = fmaxf(mx0, fmaxf(s[j][0], s[j][1]));
            mx1 = fmaxf(mx1, fmaxf(s[j][2], s[j][3]));
        }
        mx0 = fmaxf(mx0, __shfl_xor_sync(0xffffffffu, mx0, 1));
        mx0 = fmaxf(mx0, __shfl_xor_sync(0xffffffffu, mx0, 2));
        mx1 = fmaxf(mx1, __shfl_xor_sync(0xffffffffu, mx1, 1));
        mx1 = fmaxf(mx1, __shfl_xor_sync(0xffffffffu, mx1, 2));

        float mn0 = fmaxf(m0r, mx0);
        float mn1 = fmaxf(m1r, mx1);
        float al0 = exp2f(m0r - mn0);
        float al1 = exp2f(m1r - mn1);
        m0r = mn0; m1r = mn1;

        float rs0 = 0.0f, rs1 = 0.0f;
#pragma unroll
        for (int j = 0; j < 8; ++j) {
            s[j][0] = exp2f(s[j][0] - mn0);
            s[j][1] = exp2f(s[j][1] - mn0);
            s[j][2] = exp2f(s[j][2] - mn1);
            s[j][3] = exp2f(s[j][3] - mn1);
            rs0 += s[j][0] + s[j][1];
            rs1 += s[j][2] + s[j][3];
        }
        rs0 += __shfl_xor_sync(0xffffffffu, rs0, 1);
        rs0 += __shfl_xor_sync(0xffffffffu, rs0, 2);
        rs1 += __shfl_xor_sync(0xffffffffu, rs1, 1);
        rs1 += __shfl_xor_sync(0xffffffffu, rs1, 2);
        l0r = l0r * al0 + rs0;
        l1r = l1r * al1 + rs1;

#pragma unroll
        for (int j = 0; j < 8; ++j) {
            o[j][0] *= al0; o[j][1] *= al0;
            o[j][2] *= al1; o[j][3] *= al1;
        }

        // ---- pack P into fp16 hi/lo A fragments (C layout == A layout) ----
        uint32_t ph[4][4], pl[4][4];
#pragma unroll
        for (int t = 0; t < 4; ++t) {
            const float* s0 = s[2 * t];
            const float* s1 = s[2 * t + 1];
            float2 hf;
            ph[t][0] = packh(s0[0], s0[1]);
            hf = __half22float2(*(__half2*)&ph[t][0]);
            pl[t][0] = packh(s0[0] - hf.x, s0[1] - hf.y);
            ph[t][1] = packh(s0[2], s0[3]);
            hf = __half22float2(*(__half2*)&ph[t][1]);
            pl[t][1] = packh(s0[2] - hf.x, s0[3] - hf.y);
            ph[t][2] = packh(s1[0], s1[1]);
            hf = __half22float2(*(__half2*)&ph[t][2]);
            pl[t][2] = packh(s1[0] - hf.x, s1[1] - hf.y);
            ph[t][3] = packh(s1[2], s1[3]);
            hf = __half22float2(*(__half2*)&ph[t][3]);
            pl[t][3] = packh(s1[2] - hf.x, s1[3] - hf.y);
        }

        // ---- O += P @ V (2-term), V^T fragments via ldmatrix.trans ----
#pragma unroll
        for (int t = 0; t < 4; ++t) {
            uint32_t vb[8][2];
#pragma unroll
            for (int jp = 0; jp < 4; ++jp) {
                int key = t * 16 + v_key_in;
                int n16 = jp * 2 + v_n16;
                uint32_t off = SWZ128((uint32_t)(key * 128 + n16 * 16));
                ldsm_x4_t(vb[jp * 2][0], vb[jp * 2][1], vb[jp * 2 + 1][0], vb[jp * 2 + 1][1],
                          sb + 8192 + off);
            }
#pragma unroll
            for (int j = 0; j < 8; ++j) {
                mma_f16(o[j], ph[t], vb[j]);
                mma_f16(o[j], pl[t], vb[j]);
            }
        }
        __syncthreads();
    }

    // ---- epilogue: normalize, split to fp16 hi/lo, store y[B,T,D] ----
    const int b = bhid >> 4;
    const int h = bhid & 15;
    const float inv0 = 1.0f / l0r;
    const float inv1 = 1.0f / l1r;
    const int t0 = q0 + rloc0;
#pragma unroll
    for (int j = 0; j < 8; ++j) {
        int col = h * 64 + j * 8 + ((l & 3) << 1);
        size_t off0 = ((size_t)b * TT + t0) * DD + col;
        size_t off1 = ((size_t)b * TT + t0 + 8) * DD + col;
        float v0 = o[j][0] * inv0, v1 = o[j][1] * inv0;
        float v2 = o[j][2] * inv1, v3 = o[j][3] * inv1;
        __half2 h0 = __floats2half2_rn(v0, v1);
        float2 hf0 = __half22float2(h0);
        __half2 l0 = __floats2half2_rn(v0 - hf0.x, v1 - hf0.y);
        __half2 h1 = __floats2half2_rn(v2, v3);
        float2 hf1 = __half22float2(h1);
        __half2 l1 = __floats2half2_rn(v2 - hf1.x, v3 - hf1.y);
        *(__half2*)(yhi + off0) = h0;
        *(__half2*)(ylo + off0) = l0;
        *(__half2*)(yhi + off1) = h1;
        *(__half2*)(ylo + off1) = l1;
    }
}

// ---------------------------------------------------------------------------
// Launch pipeline
// ---------------------------------------------------------------------------
extern "C" void kernel_launch(void* const* d_in, const int* in_sizes, int n_in,
                              void* d_out, int out_size)
{
    (void)in_sizes; (void)n_in; (void)out_size;
    const float* x     = (const float*)d_in[0];
    // d_in[1] = causal mask, handled analytically
    const float* w_qkv = (const float*)d_in[2];
    const float* b_qkv = (const float*)d_in[3];
    const float* w_out = (const float*)d_in[4];
    const float* b_out = (const float*)d_in[5];
    float* out = (float*)d_out;

    __half *qhi, *qlo, *kh, *vh;
    __half *xhi, *xlo, *wqh, *woh, *yhi, *ylo;
    cudaGetSymbolAddress((void**)&qhi, g_qhi);
    cudaGetSymbolAddress((void**)&qlo, g_qlo);
    cudaGetSymbolAddress((void**)&kh, g_kh);
    cudaGetSymbolAddress((void**)&vh, g_vh);
    cudaGetSymbolAddress((void**)&xhi, g_xhi);
    cudaGetSymbolAddress((void**)&xlo, g_xlo);
    cudaGetSymbolAddress((void**)&wqh, g_wqh);
    cudaGetSymbolAddress((void**)&woh, g_woh);
    cudaGetSymbolAddress((void**)&yhi, g_yhi);
    cudaGetSymbolAddress((void**)&ylo, g_ylo);

    cudaFuncSetAttribute(qkv_gemm, cudaFuncAttributeMaxDynamicSharedMemorySize, GEMM_SMEM);
    cudaFuncSetAttribute(out_gemm, cudaFuncAttributeMaxDynamicSharedMemorySize, GEMM_SMEM);
    cudaFuncSetAttribute(fa_kernel, cudaFuncAttributeMaxDynamicSharedMemorySize, ATT_SMEM);

    const size_t MX = (size_t)BB * TT * DD;  // 8388608

    split_kernel<<<(unsigned)(MX / 4 / 256), 256>>>(x, xhi, xlo);
    {
        dim3 grid(3 * DD / 32, DD / 32);
        splitT_kernel<<<grid, dim3(32, 8)>>>(w_qkv, wqh, 3 * DD);
    }
    {
        dim3 grid(DD / 32, DD / 32);
        splitT_kernel<<<grid, dim3(32, 8)>>>(w_out, woh, DD);
    }

    // 1) QKV projection -> q (fp16 hi/lo, pre-scaled), k/v (fp16)
    {
        dim3 grid(3 * DD / 128, BB * TT / 128);   // (24, 64)
        qkv_gemm<<<grid, 256, GEMM_SMEM>>>(xhi, xlo, wqh, b_qkv, qhi, qlo, kh, vh);
    }

    // 2) tensor-core causal flash attention -> y fp16 hi/lo
    {
        dim3 grid(TT / 64, BB * HH);
        fa_kernel<<<grid, 128, ATT_SMEM>>>(qhi, qlo, kh, vh, yhi, ylo);
    }

    // 3) output projection -> fp32 out
    {
        dim3 grid(DD / 128, BB * TT / 128);       // (8, 64)
        out_gemm<<<grid, 256, GEMM_SMEM>>>(yhi, ylo, woh, b_out, out);
    }
}